// round 4
// baseline (speedup 1.0000x reference)
#include <cuda_runtime.h>

#define B_      64
#define WVEC    50890
#define NTEST   10000
#define INPUT_  784
#define HIDDEN_ 64
#define OUT_    10
// weight vector offsets
#define O1 50176   // end of W1 (64*784)
#define O2 50240   // end of B1
#define O3 50880   // end of W2 (10*64)

__device__ double g_acc1;
__device__ double g_acc2;

__global__ void init_k() { g_acc1 = 0.0; g_acc2 = 0.0; }

// ---------------- loss1: 20 * mean((inp1-tar1)^2) ----------------
__global__ __launch_bounds__(256) void loss1_k(const float* __restrict__ a,
                                               const float* __restrict__ t) {
    const int total4 = (B_ * WVEC) / 4;   // 814240, exact
    float s = 0.f;
    for (int i = blockIdx.x * blockDim.x + threadIdx.x; i < total4;
         i += gridDim.x * blockDim.x) {
        float4 x = ((const float4*)a)[i];
        float4 y = ((const float4*)t)[i];
        float d0 = x.x - y.x, d1 = x.y - y.y, d2 = x.z - y.z, d3 = x.w - y.w;
        s += d0 * d0 + d1 * d1 + d2 * d2 + d3 * d3;
    }
    #pragma unroll
    for (int off = 16; off; off >>= 1) s += __shfl_down_sync(0xffffffffu, s, off);
    __shared__ float ws[8];
    int lane = threadIdx.x & 31, w = threadIdx.x >> 5;
    if (lane == 0) ws[w] = s;
    __syncthreads();
    if (threadIdx.x == 0) {
        float tot = 0.f;
        #pragma unroll
        for (int i = 0; i < 8; i++) tot += ws[i];
        atomicAdd(&g_acc1, (double)tot);
    }
}

// ---------------- fused MLP forward + CE ----------------
// Block: 128 threads, tile = 128 images x 64 hidden, one batch-element b.
// Stage 1: tiled SGEMM  H = relu(images @ W1^T + B1)
// Stage 2: logits = H @ W2^T + B2, log-softmax CE, block-reduce into g_acc2.
__global__ __launch_bounds__(128) void mlp_ce_k(const float* __restrict__ images,
                                                const float* __restrict__ w,
                                                const int* __restrict__ tar2) {
    const int b  = blockIdx.y;
    const int n0 = blockIdx.x * 128;
    const float* Wb = w + (size_t)b * WVEC;   // NOTE: only 8-byte aligned (WVEC%4==2)

    __shared__ float As[16][128];     // A^T tile: [k][n]
    __shared__ float Bs[16][64];      // W1^T tile: [k][j]
    __shared__ float Hs[128][65];     // hidden activations (+pad)
    __shared__ float w2s[OUT_ * HIDDEN_];
    __shared__ float b1s[HIDDEN_];
    __shared__ float b2s[OUT_];
    __shared__ float warpsum[4];

    const int tid = threadIdx.x;

    // preamble: W2, B1, B2 into smem (scalar loads: alignment-safe)
    for (int i = tid; i < OUT_ * HIDDEN_; i += 128) w2s[i] = Wb[O2 + i];
    if (tid < HIDDEN_) b1s[tid] = Wb[O1 + tid];
    if (tid < OUT_)    b2s[tid] = Wb[O3 + tid];

    // fragment mapping: 4 warps in 2(n) x 2(j); within warp 8(n) x 4(j) lanes; 8x8 per thread
    const int warp = tid >> 5, lane = tid & 31;
    const int warpn = warp & 1, warpj = warp >> 1;
    const int ln = lane & 7, lj = lane >> 3;
    const int tn = warpn * 64 + ln * 8;   // image base within tile
    const int tj = warpj * 32 + lj * 8;   // hidden base within tile

    float acc[8][8];
    #pragma unroll
    for (int i = 0; i < 8; i++)
        #pragma unroll
        for (int j = 0; j < 8; j++) acc[i][j] = 0.f;

    for (int k0 = 0; k0 < INPUT_; k0 += 16) {
        // load A tile (128 x 16), transposed store — float4 (16B-aligned: row stride 784)
        #pragma unroll
        for (int rep = 0; rep < 4; rep++) {
            int v = rep * 128 + tid;
            int n = v >> 2, q = v & 3;
            int gn = n0 + n; if (gn > NTEST - 1) gn = NTEST - 1;
            float4 d = *(const float4*)(images + (size_t)gn * INPUT_ + k0 + q * 4);
            As[q * 4 + 0][n] = d.x; As[q * 4 + 1][n] = d.y;
            As[q * 4 + 2][n] = d.z; As[q * 4 + 3][n] = d.w;
        }
        // load B tile (64 x 16), transposed store — float2 (Wb only 8B-aligned)
        #pragma unroll
        for (int rep = 0; rep < 4; rep++) {
            int v = rep * 128 + tid;         // 512 float2 loads = 1024 elems
            int j = v >> 3, q = v & 7;
            float2 d = *(const float2*)(Wb + j * INPUT_ + k0 + q * 2);
            Bs[q * 2 + 0][j] = d.x;
            Bs[q * 2 + 1][j] = d.y;
        }
        __syncthreads();
        #pragma unroll
        for (int kk = 0; kk < 16; kk++) {
            float a[8], bb[8];
            *(float4*)&a[0]  = *(const float4*)&As[kk][tn];
            *(float4*)&a[4]  = *(const float4*)&As[kk][tn + 4];
            *(float4*)&bb[0] = *(const float4*)&Bs[kk][tj];
            *(float4*)&bb[4] = *(const float4*)&Bs[kk][tj + 4];
            #pragma unroll
            for (int i = 0; i < 8; i++)
                #pragma unroll
                for (int j = 0; j < 8; j++) acc[i][j] = fmaf(a[i], bb[j], acc[i][j]);
        }
        __syncthreads();
    }

    // bias + relu -> Hs
    #pragma unroll
    for (int i = 0; i < 8; i++)
        #pragma unroll
        for (int j = 0; j < 8; j++)
            Hs[tn + i][tj + j] = fmaxf(acc[i][j] + b1s[tj + j], 0.f);
    __syncthreads();

    // stage 2: one image per thread
    const int n = tid;
    float logits[OUT_];
    #pragma unroll
    for (int o = 0; o < OUT_; o++) logits[o] = b2s[o];
    #pragma unroll 4
    for (int j = 0; j < HIDDEN_; j++) {
        float hv = Hs[n][j];
        #pragma unroll
        for (int o = 0; o < OUT_; o++) logits[o] = fmaf(hv, w2s[o * HIDDEN_ + j], logits[o]);
    }

    float ce = 0.f;
    const int gn = n0 + n;
    if (gn < NTEST) {
        float m = logits[0];
        #pragma unroll
        for (int o = 1; o < OUT_; o++) m = fmaxf(m, logits[o]);
        float s = 0.f;
        #pragma unroll
        for (int o = 0; o < OUT_; o++) s += expf(logits[o] - m);
        float lse = m + logf(s);
        int t = tar2[(size_t)b * NTEST + gn];   // int32 targets (JAX x64 disabled)
        float picked = 0.f;
        #pragma unroll
        for (int o = 0; o < OUT_; o++) picked = (o == t) ? logits[o] : picked;
        ce = lse - picked;
    }
    #pragma unroll
    for (int off = 16; off; off >>= 1) ce += __shfl_down_sync(0xffffffffu, ce, off);
    if (lane == 0) warpsum[warp] = ce;
    __syncthreads();
    if (tid == 0) {
        float tot = warpsum[0] + warpsum[1] + warpsum[2] + warpsum[3];
        atomicAdd(&g_acc2, (double)tot);
    }
}

// ---------------- finalize ----------------
__global__ void fin_k(float* __restrict__ out) {
    float l1 = (float)(20.0 * (g_acc1 / (double)((size_t)B_ * WVEC)));
    float l2 = (float)(g_acc2 / (double)((size_t)B_ * NTEST));
    out[0] = l1 + l2;
    out[1] = l1;
    out[2] = l2;
}

extern "C" void kernel_launch(void* const* d_in, const int* in_sizes, int n_in,
                              void* d_out, int out_size) {
    const float* inp1   = (const float*)d_in[0];
    const float* tar1   = (const float*)d_in[1];
    const float* inp2   = (const float*)d_in[2];
    const int*   tar2   = (const int*)d_in[3];
    const float* images = (const float*)d_in[4];
    float* out = (float*)d_out;

    init_k<<<1, 1>>>();
    loss1_k<<<1024, 256>>>(inp1, tar1);
    dim3 grid((NTEST + 127) / 128, B_);
    mlp_ce_k<<<grid, 128>>>(images, inp2, tar2);
    fin_k<<<1, 1>>>(out);
}

// round 6
// speedup vs baseline: 5.1807x; 5.1807x over previous
#include <cuda_runtime.h>
#include <cuda_bf16.h>
#include <cstdint>

#define B_      64
#define WVEC    50890
#define NTEST   10000
#define INPUT_  784
#define KPAD    800
#define HIDDEN_ 64
#define OUT_    10
#define O1 50176
#define O2 50240
#define O3 50880
#define NTILE_  79    // ceil(10000/128)

__device__ double g_acc1;
__device__ double g_acc2;
__device__ __nv_bfloat16 g_imgs_bf[NTEST * KPAD];          // 16 MB (K zero-padded)
__device__ __nv_bfloat16 g_w1_bf[B_ * HIDDEN_ * KPAD];     // 6.6 MB

// ---------------- prep: fp32 -> bf16 with K-pad to 800 ----------------
__global__ __launch_bounds__(256) void conv_imgs_k(const float* __restrict__ images) {
    if (blockIdx.x == 0 && threadIdx.x == 0) { g_acc1 = 0.0; g_acc2 = 0.0; }
    const int total = NTEST * KPAD / 2;        // 4,000,000 bf162
    __nv_bfloat162* dst = (__nv_bfloat162*)g_imgs_bf;
    for (int i = blockIdx.x * blockDim.x + threadIdx.x; i < total;
         i += gridDim.x * blockDim.x) {
        int p = i % (KPAD / 2), row = i / (KPAD / 2);
        int k = 2 * p;
        __nv_bfloat162 v;
        if (k < INPUT_) {
            float2 f = *(const float2*)(images + (size_t)row * INPUT_ + k);
            v = __floats2bfloat162_rn(f.x, f.y);
        } else {
            v = __floats2bfloat162_rn(0.f, 0.f);
        }
        dst[i] = v;
    }
}
__global__ __launch_bounds__(256) void conv_w1_k(const float* __restrict__ w) {
    const int total = B_ * HIDDEN_ * KPAD / 2;   // 1,638,400 bf162
    __nv_bfloat162* dst = (__nv_bfloat162*)g_w1_bf;
    for (int i = blockIdx.x * blockDim.x + threadIdx.x; i < total;
         i += gridDim.x * blockDim.x) {
        int p = i % (KPAD / 2), r = i / (KPAD / 2);
        int b = r >> 6, j = r & 63;
        int k = 2 * p;
        __nv_bfloat162 v;
        if (k < INPUT_) {
            float2 f = *(const float2*)(w + (size_t)b * WVEC + j * INPUT_ + k);
            v = __floats2bfloat162_rn(f.x, f.y);
        } else {
            v = __floats2bfloat162_rn(0.f, 0.f);
        }
        dst[i] = v;
    }
}

// ---------------- loss1 ----------------
__global__ __launch_bounds__(256) void loss1_k(const float* __restrict__ a,
                                               const float* __restrict__ t) {
    const int total4 = (B_ * WVEC) / 4;
    float s = 0.f;
    for (int i = blockIdx.x * blockDim.x + threadIdx.x; i < total4;
         i += gridDim.x * blockDim.x) {
        float4 x = ((const float4*)a)[i];
        float4 y = ((const float4*)t)[i];
        float d0 = x.x - y.x, d1 = x.y - y.y, d2 = x.z - y.z, d3 = x.w - y.w;
        s += d0 * d0 + d1 * d1 + d2 * d2 + d3 * d3;
    }
    #pragma unroll
    for (int off = 16; off; off >>= 1) s += __shfl_down_sync(0xffffffffu, s, off);
    __shared__ float ws[8];
    int lane = threadIdx.x & 31, w = threadIdx.x >> 5;
    if (lane == 0) ws[w] = s;
    __syncthreads();
    if (threadIdx.x == 0) {
        float tot = 0.f;
        #pragma unroll
        for (int i = 0; i < 8; i++) tot += ws[i];
        atomicAdd(&g_acc1, (double)tot);
    }
}

// ---------------- bf16 mma.sync MLP forward + CE ----------------
// CTA: 256 thr (8 warps = 4 m-strips x 2 b). Tile M=128 imgs, N=2x64 hidden, K=800.
// Warp (wm,wn): rows [wm*32, wm*32+32), batch b = 2*bp + wn, all 64 hidden of that b.
__global__ __launch_bounds__(256) void mlp_ce_mma_k(const float* __restrict__ w,
                                                    const int* __restrict__ tar2) {
    const int bp = blockIdx.y;
    const int n0 = blockIdx.x * 128;

    __shared__ __nv_bfloat16 sA[128 * 40];   // stride 40 bf16 (80B): conflict-free
    __shared__ __nv_bfloat16 sB[128 * 40];   // rows 0-63: b0, 64-127: b1
    __shared__ float w2s[2 * OUT_ * HIDDEN_];
    __shared__ float b1s[2 * HIDDEN_];
    __shared__ float b2s[2 * OUT_];
    __shared__ float warpsum[8];

    const int tid = threadIdx.x, wid = tid >> 5, lane = tid & 31;
    const int wm = wid & 3, wn = wid >> 2;
    const int g = lane >> 2, t = lane & 3;

    // preamble: fp32 stage-2 weights for both b's (scalar: alignment-safe)
    #pragma unroll 1
    for (int i = tid; i < 2 * OUT_ * HIDDEN_; i += 256) {
        int bb = i / (OUT_ * HIDDEN_), r = i % (OUT_ * HIDDEN_);
        w2s[i] = w[(size_t)(2 * bp + bb) * WVEC + O2 + r];
    }
    if (tid < 128) b1s[tid] = w[(size_t)(2 * bp + (tid >> 6)) * WVEC + O1 + (tid & 63)];
    if (tid < 20)  b2s[tid] = w[(size_t)(2 * bp + (tid >= 10)) * WVEC + O3 + (tid % 10)];

    float acc[2][8][4];
    #pragma unroll
    for (int mt = 0; mt < 2; mt++)
        #pragma unroll
        for (int nt = 0; nt < 8; nt++)
            #pragma unroll
            for (int r = 0; r < 4; r++) acc[mt][nt][r] = 0.f;

    const __nv_bfloat16* Ab = g_imgs_bf;
    const __nv_bfloat16* Bb = g_w1_bf + (size_t)(2 * bp) * HIDDEN_ * KPAD;

    const int rowL = tid >> 2, q = tid & 3;     // 64 rows per 256-thread pass
    const int rowH = rowL + 64;
    int gnL = n0 + rowL; if (gnL > NTEST - 1) gnL = NTEST - 1;
    int gnH = n0 + rowH; if (gnH > NTEST - 1) gnH = NTEST - 1;

    for (int c = 0; c < 25; c++) {
        const int k0 = c * 32;
        // A tile 128x32, B tile 128x32 (two b's contiguous in g_w1_bf)
        *(uint4*)&sA[rowL * 40 + q * 8] = *(const uint4*)(Ab + (size_t)gnL * KPAD + k0 + q * 8);
        *(uint4*)&sA[rowH * 40 + q * 8] = *(const uint4*)(Ab + (size_t)gnH * KPAD + k0 + q * 8);
        *(uint4*)&sB[rowL * 40 + q * 8] = *(const uint4*)(Bb + (size_t)rowL * KPAD + k0 + q * 8);
        *(uint4*)&sB[rowH * 40 + q * 8] = *(const uint4*)(Bb + (size_t)rowH * KPAD + k0 + q * 8);
        __syncthreads();
        #pragma unroll
        for (int ks = 0; ks < 32; ks += 16) {
            uint32_t a[2][4], bf[8][2];
            #pragma unroll
            for (int mt = 0; mt < 2; mt++) {
                int base = (wm * 32 + mt * 16 + g) * 40 + ks + 2 * t;
                a[mt][0] = *(const uint32_t*)&sA[base];
                a[mt][1] = *(const uint32_t*)&sA[base + 8 * 40];
                a[mt][2] = *(const uint32_t*)&sA[base + 8];
                a[mt][3] = *(const uint32_t*)&sA[base + 8 * 40 + 8];
            }
            #pragma unroll
            for (int nt = 0; nt < 8; nt++) {
                int base = (wn * 64 + nt * 8 + g) * 40 + ks + 2 * t;
                bf[nt][0] = *(const uint32_t*)&sB[base];
                bf[nt][1] = *(const uint32_t*)&sB[base + 8];
            }
            #pragma unroll
            for (int mt = 0; mt < 2; mt++)
                #pragma unroll
                for (int nt = 0; nt < 8; nt++)
                    asm volatile(
                        "mma.sync.aligned.m16n8k16.row.col.f32.bf16.bf16.f32 "
                        "{%0,%1,%2,%3},{%4,%5,%6,%7},{%8,%9},{%0,%1,%2,%3};"
                        : "+f"(acc[mt][nt][0]), "+f"(acc[mt][nt][1]),
                          "+f"(acc[mt][nt][2]), "+f"(acc[mt][nt][3])
                        : "r"(a[mt][0]), "r"(a[mt][1]), "r"(a[mt][2]), "r"(a[mt][3]),
                          "r"(bf[nt][0]), "r"(bf[nt][1]));
        }
        __syncthreads();
    }

    // ---- stage 2 straight from fragments ----
    // thread holds rows {wm*32+mt*16+g+8h}, cols j = nt*8+2t+e of batch b=2bp+wn
    float lg[4][OUT_];
    #pragma unroll
    for (int r = 0; r < 4; r++)
        #pragma unroll
        for (int o = 0; o < OUT_; o++) lg[r][o] = 0.f;

    #pragma unroll
    for (int nt = 0; nt < 8; nt++) {
        #pragma unroll
        for (int e = 0; e < 2; e++) {
            const int j = nt * 8 + 2 * t + e;
            const float bias = b1s[wn * 64 + j];
            float wv[OUT_];
            #pragma unroll
            for (int o = 0; o < OUT_; o++) wv[o] = w2s[wn * 640 + o * 64 + j];
            #pragma unroll
            for (int mt = 0; mt < 2; mt++)
                #pragma unroll
                for (int h = 0; h < 2; h++) {
                    float hv = fmaxf(acc[mt][nt][h * 2 + e] + bias, 0.f);
                    #pragma unroll
                    for (int o = 0; o < OUT_; o++)
                        lg[mt * 2 + h][o] = fmaf(hv, wv[o], lg[mt * 2 + h][o]);
                }
        }
    }
    // quad reduce (lanes t=0..3 share a row)
    #pragma unroll
    for (int r = 0; r < 4; r++)
        #pragma unroll
        for (int o = 0; o < OUT_; o++) {
            lg[r][o] += __shfl_xor_sync(0xffffffffu, lg[r][o], 1);
            lg[r][o] += __shfl_xor_sync(0xffffffffu, lg[r][o], 2);
        }

    float ce = 0.f;
    if (t == 0) {
        const int bidx = 2 * bp + wn;
        #pragma unroll
        for (int mt = 0; mt < 2; mt++)
            #pragma unroll
            for (int h = 0; h < 2; h++) {
                const int gn = n0 + wm * 32 + mt * 16 + g + 8 * h;
                if (gn < NTEST) {
                    float logits[OUT_];
                    #pragma unroll
                    for (int o = 0; o < OUT_; o++)
                        logits[o] = lg[mt * 2 + h][o] + b2s[wn * 10 + o];
                    float m = logits[0];
                    #pragma unroll
                    for (int o = 1; o < OUT_; o++) m = fmaxf(m, logits[o]);
                    float s = 0.f;
                    #pragma unroll
                    for (int o = 0; o < OUT_; o++) s += expf(logits[o] - m);
                    float lse = m + logf(s);
                    int tg = tar2[(size_t)bidx * NTEST + gn];
                    float picked = 0.f;
                    #pragma unroll
                    for (int o = 0; o < OUT_; o++) picked = (o == tg) ? logits[o] : picked;
                    ce += lse - picked;
                }
            }
    }
    #pragma unroll
    for (int off = 16; off; off >>= 1) ce += __shfl_down_sync(0xffffffffu, ce, off);
    if (lane == 0) warpsum[wid] = ce;
    __syncthreads();
    if (tid == 0) {
        float tot = 0.f;
        #pragma unroll
        for (int i = 0; i < 8; i++) tot += warpsum[i];
        atomicAdd(&g_acc2, (double)tot);
    }
}

// ---------------- finalize ----------------
__global__ void fin_k(float* __restrict__ out) {
    float l1 = (float)(20.0 * (g_acc1 / (double)((size_t)B_ * WVEC)));
    float l2 = (float)(g_acc2 / (double)((size_t)B_ * NTEST));
    out[0] = l1 + l2;
    out[1] = l1;
    out[2] = l2;
}

extern "C" void kernel_launch(void* const* d_in, const int* in_sizes, int n_in,
                              void* d_out, int out_size) {
    const float* inp1   = (const float*)d_in[0];
    const float* tar1   = (const float*)d_in[1];
    const float* inp2   = (const float*)d_in[2];
    const int*   tar2   = (const int*)d_in[3];
    const float* images = (const float*)d_in[4];
    float* out = (float*)d_out;

    conv_imgs_k<<<512, 256>>>(images);
    conv_w1_k<<<512, 256>>>(inp2);
    loss1_k<<<1024, 256>>>(inp1, tar1);
    dim3 grid(NTILE_, B_ / 2);
    mlp_ce_mma_k<<<grid, 256>>>(inp2, tar2);
    fin_k<<<1, 1>>>(out);
}

// round 11
// speedup vs baseline: 5.5269x; 1.0668x over previous
#include <cuda_runtime.h>
#include <cuda_bf16.h>
#include <cstdint>

#define B_      64
#define WVEC    50890
#define NTEST   10000
#define INPUT_  784
#define KPAD    800
#define HIDDEN_ 64
#define OUT_    10
#define O1 50176
#define O2 50240
#define O3 50880
#define NTILE_  79    // ceil(10000/128)

__device__ double g_acc1;
__device__ double g_acc2;
__device__ __nv_bfloat16 g_imgs_bf[NTEST * KPAD];          // 16 MB (K zero-padded)
__device__ __nv_bfloat16 g_w1_bf[B_ * HIDDEN_ * KPAD];     // 6.6 MB

// ---------------- prep: fp32 -> bf16 with K-pad to 800 ----------------
__global__ __launch_bounds__(256) void conv_imgs_k(const float* __restrict__ images) {
    if (blockIdx.x == 0 && threadIdx.x == 0) { g_acc1 = 0.0; g_acc2 = 0.0; }
    const int total = NTEST * KPAD / 2;
    __nv_bfloat162* dst = (__nv_bfloat162*)g_imgs_bf;
    for (int i = blockIdx.x * blockDim.x + threadIdx.x; i < total;
         i += gridDim.x * blockDim.x) {
        int p = i % (KPAD / 2), row = i / (KPAD / 2);
        int k = 2 * p;
        __nv_bfloat162 v;
        if (k < INPUT_) {
            float2 f = *(const float2*)(images + (size_t)row * INPUT_ + k);
            v = __floats2bfloat162_rn(f.x, f.y);
        } else {
            v = __floats2bfloat162_rn(0.f, 0.f);
        }
        dst[i] = v;
    }
}
__global__ __launch_bounds__(256) void conv_w1_k(const float* __restrict__ w) {
    const int total = B_ * HIDDEN_ * KPAD / 2;
    __nv_bfloat162* dst = (__nv_bfloat162*)g_w1_bf;
    for (int i = blockIdx.x * blockDim.x + threadIdx.x; i < total;
         i += gridDim.x * blockDim.x) {
        int p = i % (KPAD / 2), r = i / (KPAD / 2);
        int b = r >> 6, j = r & 63;
        int k = 2 * p;
        __nv_bfloat162 v;
        if (k < INPUT_) {
            float2 f = *(const float2*)(w + (size_t)b * WVEC + j * INPUT_ + k);
            v = __floats2bfloat162_rn(f.x, f.y);
        } else {
            v = __floats2bfloat162_rn(0.f, 0.f);
        }
        dst[i] = v;
    }
}

// ---------------- loss1 ----------------
__global__ __launch_bounds__(256) void loss1_k(const float* __restrict__ a,
                                               const float* __restrict__ t) {
    const int total4 = (B_ * WVEC) / 4;
    float s = 0.f;
    for (int i = blockIdx.x * blockDim.x + threadIdx.x; i < total4;
         i += gridDim.x * blockDim.x) {
        float4 x = ((const float4*)a)[i];
        float4 y = ((const float4*)t)[i];
        float d0 = x.x - y.x, d1 = x.y - y.y, d2 = x.z - y.z, d3 = x.w - y.w;
        s += d0 * d0 + d1 * d1 + d2 * d2 + d3 * d3;
    }
    #pragma unroll
    for (int off = 16; off; off >>= 1) s += __shfl_down_sync(0xffffffffu, s, off);
    __shared__ float ws[8];
    int lane = threadIdx.x & 31, w = threadIdx.x >> 5;
    if (lane == 0) ws[w] = s;
    __syncthreads();
    if (threadIdx.x == 0) {
        float tot = 0.f;
        #pragma unroll
        for (int i = 0; i < 8; i++) tot += ws[i];
        atomicAdd(&g_acc1, (double)tot);
    }
}

__device__ __forceinline__ uint32_t smem_u32(const void* p) {
    uint32_t a;
    asm("{ .reg .u64 t; cvta.to.shared.u64 t, %1; cvt.u32.u64 %0, t; }" : "=r"(a) : "l"(p));
    return a;
}
#define CP16(dst, src) \
    asm volatile("cp.async.cg.shared.global [%0], [%1], 16;" :: "r"(dst), "l"(src))
#define CP_COMMIT() asm volatile("cp.async.commit_group;" ::: "memory")
#define CP_WAIT(n)  asm volatile("cp.async.wait_group %0;" :: "n"(n) : "memory")
#define LDSM_X4(r0, r1, r2, r3, addr) \
    asm volatile("ldmatrix.sync.aligned.m8n8.x4.shared.b16 {%0,%1,%2,%3}, [%4];" \
                 : "=r"(r0), "=r"(r1), "=r"(r2), "=r"(r3) : "r"(addr))

// ---------------- bf16 mma.sync MLP forward + CE (ldmatrix + cp.async) ----------
// CTA: 256 thr (8 warps = 4 m-strips x 2 b). Tile M=128 imgs, N=2x64 hidden, K=800.
#define TSTRIDE 40                     // bf16 elems per smem row (80 B)
#define STAGEB  (128 * TSTRIDE * 2)    // bytes per stage buffer: 10240
__global__ __launch_bounds__(256, 2) void mlp_ce_mma_k(const float* __restrict__ w,
                                                       const int* __restrict__ tar2) {
    const int bp = blockIdx.y;
    const int n0 = blockIdx.x * 128;

    __shared__ __nv_bfloat16 sA[2][128 * TSTRIDE];
    __shared__ __nv_bfloat16 sB[2][128 * TSTRIDE];
    __shared__ float w2s[2 * OUT_ * HIDDEN_];
    __shared__ float b1s[2 * HIDDEN_];
    __shared__ float b2s[2 * OUT_];
    __shared__ float warpsum[8];

    const int tid = threadIdx.x, wid = tid >> 5, lane = tid & 31;
    const int wm = wid & 3, wn = wid >> 2;
    const int g = lane >> 2, t = lane & 3;

    // stage-2 weights (scalar loads: alignment-safe)
    #pragma unroll 1
    for (int i = tid; i < 2 * OUT_ * HIDDEN_; i += 256) {
        int bb = i / (OUT_ * HIDDEN_), r = i % (OUT_ * HIDDEN_);
        w2s[i] = w[(size_t)(2 * bp + bb) * WVEC + O2 + r];
    }
    if (tid < 128) b1s[tid] = w[(size_t)(2 * bp + (tid >> 6)) * WVEC + O1 + (tid & 63)];
    if (tid < 20)  b2s[tid] = w[(size_t)(2 * bp + (tid >= 10)) * WVEC + O3 + (tid % 10)];

    float acc[2][8][4];
    #pragma unroll
    for (int mt = 0; mt < 2; mt++)
        #pragma unroll
        for (int nt = 0; nt < 8; nt++)
            #pragma unroll
            for (int r = 0; r < 4; r++) acc[mt][nt][r] = 0.f;

    const __nv_bfloat16* Ab = g_imgs_bf;
    const __nv_bfloat16* Bb = g_w1_bf + (size_t)(2 * bp) * HIDDEN_ * KPAD;

    // cp.async mapping: 2 threads/row, 2x16B chunks each (row = 32 bf16 = 64 B)
    // half h = tid&1 copies chunks {2h, 2h+1}: elem offsets 16h and 16h+8
    const int rowT = tid >> 1, eT = (tid & 1) * 16;
    int gnT = n0 + rowT; if (gnT > NTEST - 1) gnT = NTEST - 1;
    const __nv_bfloat16* srcA = Ab + (size_t)gnT * KPAD + eT;
    const __nv_bfloat16* srcB = Bb + (size_t)rowT * KPAD + eT;
    const uint32_t sA_u = smem_u32(sA);
    const uint32_t sB_u = smem_u32(sB);
    const uint32_t dstA = sA_u + (rowT * TSTRIDE + eT) * 2;
    const uint32_t dstB = sB_u + (rowT * TSTRIDE + eT) * 2;

    // ldmatrix base addresses (stage 0, ks = 0)
    uint32_t aAddr[2], bAddr[4];
    #pragma unroll
    for (int mt = 0; mt < 2; mt++)
        aAddr[mt] = sA_u + (((wm * 32 + mt * 16 + (lane & 15)) * TSTRIDE) +
                            ((lane >> 4) * 8)) * 2;
    #pragma unroll
    for (int ntp = 0; ntp < 4; ntp++)
        bAddr[ntp] = sB_u + (((wn * 64 + ntp * 16 + ((lane >> 4) * 8) + (lane & 7)) * TSTRIDE) +
                             (((lane >> 3) & 1) * 8)) * 2;

    // prologue: stage 0
    CP16(dstA,      srcA);
    CP16(dstA + 16, srcA + 8);
    CP16(dstB,      srcB);
    CP16(dstB + 16, srcB + 8);
    CP_COMMIT();

    for (int c = 0; c < 25; c++) {
        const uint32_t stOff = (uint32_t)(c & 1) * STAGEB;
        if (c < 24) {
            const uint32_t pOff = (uint32_t)((c + 1) & 1) * STAGEB;
            const int k0 = (c + 1) * 32;
            CP16(dstA + pOff,      srcA + k0);
            CP16(dstA + pOff + 16, srcA + k0 + 8);
            CP16(dstB + pOff,      srcB + k0);
            CP16(dstB + pOff + 16, srcB + k0 + 8);
            CP_COMMIT();
            CP_WAIT(1);
        } else {
            CP_WAIT(0);
        }
        __syncthreads();

        #pragma unroll
        for (int ks = 0; ks < 2; ks++) {
            const uint32_t ko = stOff + ks * 32;   // 16 bf16 = 32 B
            uint32_t a[2][4], bf[8][2];
            LDSM_X4(a[0][0], a[0][1], a[0][2], a[0][3], aAddr[0] + ko);
            LDSM_X4(a[1][0], a[1][1], a[1][2], a[1][3], aAddr[1] + ko);
            // B tiles: smem rows are already the n-dimension -> NON-trans
            LDSM_X4(bf[0][0], bf[0][1], bf[1][0], bf[1][1], bAddr[0] + ko);
            LDSM_X4(bf[2][0], bf[2][1], bf[3][0], bf[3][1], bAddr[1] + ko);
            LDSM_X4(bf[4][0], bf[4][1], bf[5][0], bf[5][1], bAddr[2] + ko);
            LDSM_X4(bf[6][0], bf[6][1], bf[7][0], bf[7][1], bAddr[3] + ko);
            #pragma unroll
            for (int mt = 0; mt < 2; mt++)
                #pragma unroll
                for (int nt = 0; nt < 8; nt++)
                    asm volatile(
                        "mma.sync.aligned.m16n8k16.row.col.f32.bf16.bf16.f32 "
                        "{%0,%1,%2,%3},{%4,%5,%6,%7},{%8,%9},{%0,%1,%2,%3};"
                        : "+f"(acc[mt][nt][0]), "+f"(acc[mt][nt][1]),
                          "+f"(acc[mt][nt][2]), "+f"(acc[mt][nt][3])
                        : "r"(a[mt][0]), "r"(a[mt][1]), "r"(a[mt][2]), "r"(a[mt][3]),
                          "r"(bf[nt][0]), "r"(bf[nt][1]));
        }
        __syncthreads();
    }

    // ---- stage 2 straight from fragments ----
    float lg[4][OUT_];
    #pragma unroll
    for (int r = 0; r < 4; r++)
        #pragma unroll
        for (int o = 0; o < OUT_; o++) lg[r][o] = 0.f;

    #pragma unroll
    for (int nt = 0; nt < 8; nt++) {
        #pragma unroll
        for (int e = 0; e < 2; e++) {
            const int j = nt * 8 + 2 * t + e;
            const float bias = b1s[wn * 64 + j];
            float wv[OUT_];
            #pragma unroll
            for (int o = 0; o < OUT_; o++) wv[o] = w2s[wn * 640 + o * 64 + j];
            #pragma unroll
            for (int mt = 0; mt < 2; mt++)
                #pragma unroll
                for (int h = 0; h < 2; h++) {
                    float hv = fmaxf(acc[mt][nt][h * 2 + e] + bias, 0.f);
                    #pragma unroll
                    for (int o = 0; o < OUT_; o++)
                        lg[mt * 2 + h][o] = fmaf(hv, wv[o], lg[mt * 2 + h][o]);
                }
        }
    }
    #pragma unroll
    for (int r = 0; r < 4; r++)
        #pragma unroll
        for (int o = 0; o < OUT_; o++) {
            lg[r][o] += __shfl_xor_sync(0xffffffffu, lg[r][o], 1);
            lg[r][o] += __shfl_xor_sync(0xffffffffu, lg[r][o], 2);
        }

    float ce = 0.f;
    if (t == 0) {
        const int bidx = 2 * bp + wn;
        #pragma unroll
        for (int mt = 0; mt < 2; mt++)
            #pragma unroll
            for (int h = 0; h < 2; h++) {
                const int gn = n0 + wm * 32 + mt * 16 + g + 8 * h;
                if (gn < NTEST) {
                    float logits[OUT_];
                    #pragma unroll
                    for (int o = 0; o < OUT_; o++)
                        logits[o] = lg[mt * 2 + h][o] + b2s[wn * 10 + o];
                    float m = logits[0];
                    #pragma unroll
                    for (int o = 1; o < OUT_; o++) m = fmaxf(m, logits[o]);
                    float s = 0.f;
                    #pragma unroll
                    for (int o = 0; o < OUT_; o++) s += expf(logits[o] - m);
                    float lse = m + logf(s);
                    int tg = tar2[(size_t)bidx * NTEST + gn];
                    float picked = 0.f;
                    #pragma unroll
                    for (int o = 0; o < OUT_; o++) picked = (o == tg) ? logits[o] : picked;
                    ce += lse - picked;
                }
            }
    }
    #pragma unroll
    for (int off = 16; off; off >>= 1) ce += __shfl_down_sync(0xffffffffu, ce, off);
    if (lane == 0) warpsum[wid] = ce;
    __syncthreads();
    if (tid == 0) {
        float tot = 0.f;
        #pragma unroll
        for (int i = 0; i < 8; i++) tot += warpsum[i];
        atomicAdd(&g_acc2, (double)tot);
    }
}

// ---------------- finalize ----------------
__global__ void fin_k(float* __restrict__ out) {
    float l1 = (float)(20.0 * (g_acc1 / (double)((size_t)B_ * WVEC)));
    float l2 = (float)(g_acc2 / (double)((size_t)B_ * NTEST));
    out[0] = l1 + l2;
    out[1] = l1;
    out[2] = l2;
}

extern "C" void kernel_launch(void* const* d_in, const int* in_sizes, int n_in,
                              void* d_out, int out_size) {
    const float* inp1   = (const float*)d_in[0];
    const float* tar1   = (const float*)d_in[1];
    const float* inp2   = (const float*)d_in[2];
    const int*   tar2   = (const int*)d_in[3];
    const float* images = (const float*)d_in[4];
    float* out = (float*)d_out;

    conv_imgs_k<<<512, 256>>>(images);
    conv_w1_k<<<512, 256>>>(inp2);
    loss1_k<<<1024, 256>>>(inp1, tar1);
    dim3 grid(NTILE_, B_ / 2);
    mlp_ce_mma_k<<<grid, 256>>>(inp2, tar2);
    fin_k<<<1, 1>>>(out);
}

// round 13
// speedup vs baseline: 6.1690x; 1.1162x over previous
#include <cuda_runtime.h>
#include <cuda_bf16.h>
#include <cstdint>

#define B_      64
#define WVEC    50890
#define NTEST   10000
#define INPUT_  784
#define KPAD    800
#define HIDDEN_ 64
#define OUT_    10
#define O1 50176
#define O2 50240
#define O3 50880
#define NTILE_  79    // ceil(10000/128)
#define PREPB   1024  // prep kernel blocks

__device__ double g_acc2;
__device__ float  g_l1part[PREPB];
__device__ __nv_bfloat16 g_imgs_bf[NTEST * KPAD];          // 16 MB (K zero-padded)
__device__ __nv_bfloat16 g_w1_bf[B_ * HIDDEN_ * KPAD];     // 6.6 MB

// ---------------- fused prep: conversions + loss1 partials ----------------
__global__ __launch_bounds__(256) void prep_k(const float* __restrict__ images,
                                              const float* __restrict__ w,
                                              const float* __restrict__ a,
                                              const float* __restrict__ t) {
    if (blockIdx.x == 0 && threadIdx.x == 0) g_acc2 = 0.0;
    const int gtid = blockIdx.x * blockDim.x + threadIdx.x;
    const int gstr = gridDim.x * blockDim.x;

    // images fp32 -> bf16, K padded to 800
    {
        const int total = NTEST * KPAD / 2;
        __nv_bfloat162* dst = (__nv_bfloat162*)g_imgs_bf;
        for (int i = gtid; i < total; i += gstr) {
            int p = i % (KPAD / 2), row = i / (KPAD / 2);
            int k = 2 * p;
            __nv_bfloat162 v;
            if (k < INPUT_) {
                float2 f = *(const float2*)(images + (size_t)row * INPUT_ + k);
                v = __floats2bfloat162_rn(f.x, f.y);
            } else {
                v = __floats2bfloat162_rn(0.f, 0.f);
            }
            dst[i] = v;
        }
    }
    // W1 fp32 -> bf16, K padded
    {
        const int total = B_ * HIDDEN_ * KPAD / 2;
        __nv_bfloat162* dst = (__nv_bfloat162*)g_w1_bf;
        for (int i = gtid; i < total; i += gstr) {
            int p = i % (KPAD / 2), r = i / (KPAD / 2);
            int b = r >> 6, j = r & 63;
            int k = 2 * p;
            __nv_bfloat162 v;
            if (k < INPUT_) {
                float2 f = *(const float2*)(w + (size_t)b * WVEC + j * INPUT_ + k);
                v = __floats2bfloat162_rn(f.x, f.y);
            } else {
                v = __floats2bfloat162_rn(0.f, 0.f);
            }
            dst[i] = v;
        }
    }
    // loss1 partial sum for this block
    {
        const int total4 = (B_ * WVEC) / 4;
        float s = 0.f;
        for (int i = gtid; i < total4; i += gstr) {
            float4 x = ((const float4*)a)[i];
            float4 y = ((const float4*)t)[i];
            float d0 = x.x - y.x, d1 = x.y - y.y, d2 = x.z - y.z, d3 = x.w - y.w;
            s += d0 * d0 + d1 * d1 + d2 * d2 + d3 * d3;
        }
        #pragma unroll
        for (int off = 16; off; off >>= 1) s += __shfl_down_sync(0xffffffffu, s, off);
        __shared__ float ws[8];
        int lane = threadIdx.x & 31, wrp = threadIdx.x >> 5;
        if (lane == 0) ws[wrp] = s;
        __syncthreads();
        if (threadIdx.x == 0) {
            float tot = 0.f;
            #pragma unroll
            for (int i = 0; i < 8; i++) tot += ws[i];
            g_l1part[blockIdx.x] = tot;
        }
    }
}

__device__ __forceinline__ uint32_t smem_u32(const void* p) {
    uint32_t a;
    asm("{ .reg .u64 t; cvta.to.shared.u64 t, %1; cvt.u32.u64 %0, t; }" : "=r"(a) : "l"(p));
    return a;
}
#define CP16(dst, src) \
    asm volatile("cp.async.cg.shared.global [%0], [%1], 16;" :: "r"(dst), "l"(src))
#define CP_COMMIT() asm volatile("cp.async.commit_group;" ::: "memory")
#define CP_WAIT(n)  asm volatile("cp.async.wait_group %0;" :: "n"(n) : "memory")
#define LDSM_X4(r0, r1, r2, r3, addr) \
    asm volatile("ldmatrix.sync.aligned.m8n8.x4.shared.b16 {%0,%1,%2,%3}, [%4];" \
                 : "=r"(r0), "=r"(r1), "=r"(r2), "=r"(r3) : "r"(addr))

// ---------------- bf16 mma.sync MLP forward + CE (single-sync pipeline) --------
// CTA: 256 thr (8 warps = 4 m-strips x 2 b). Tile M=128 imgs, N=2x64 hidden, K=800.
#define TSTRIDE 40                     // bf16 elems per smem row (80 B)
#define STAGEB  (128 * TSTRIDE * 2)    // bytes per stage buffer: 10240
__global__ __launch_bounds__(256, 2) void mlp_ce_mma_k(const float* __restrict__ w,
                                                       const int* __restrict__ tar2) {
    const int bp = blockIdx.y;
    const int n0 = blockIdx.x * 128;

    __shared__ __nv_bfloat16 sA[2][128 * TSTRIDE];
    __shared__ __nv_bfloat16 sB[2][128 * TSTRIDE];
    __shared__ float w2s[2 * OUT_ * HIDDEN_];
    __shared__ float b1s[2 * HIDDEN_];
    __shared__ float b2s[2 * OUT_];
    __shared__ float warpsum[8];

    const int tid = threadIdx.x, wid = tid >> 5, lane = tid & 31;
    const int wm = wid & 3, wn = wid >> 2;
    const int g = lane >> 2, t = lane & 3;

    // stage-2 weights (scalar loads: alignment-safe)
    #pragma unroll 1
    for (int i = tid; i < 2 * OUT_ * HIDDEN_; i += 256) {
        int bb = i / (OUT_ * HIDDEN_), r = i % (OUT_ * HIDDEN_);
        w2s[i] = w[(size_t)(2 * bp + bb) * WVEC + O2 + r];
    }
    if (tid < 128) b1s[tid] = w[(size_t)(2 * bp + (tid >> 6)) * WVEC + O1 + (tid & 63)];
    if (tid < 20)  b2s[tid] = w[(size_t)(2 * bp + (tid >= 10)) * WVEC + O3 + (tid % 10)];

    float acc[2][8][4];
    #pragma unroll
    for (int mt = 0; mt < 2; mt++)
        #pragma unroll
        for (int nt = 0; nt < 8; nt++)
            #pragma unroll
            for (int r = 0; r < 4; r++) acc[mt][nt][r] = 0.f;

    const __nv_bfloat16* Ab = g_imgs_bf;
    const __nv_bfloat16* Bb = g_w1_bf + (size_t)(2 * bp) * HIDDEN_ * KPAD;

    // cp.async mapping: 2 threads/row, 2x16B chunks each (row = 32 bf16 = 64 B)
    const int rowT = tid >> 1, eT = (tid & 1) * 16;
    int gnT = n0 + rowT; if (gnT > NTEST - 1) gnT = NTEST - 1;
    const __nv_bfloat16* srcA = Ab + (size_t)gnT * KPAD + eT;
    const __nv_bfloat16* srcB = Bb + (size_t)rowT * KPAD + eT;
    const uint32_t sA_u = smem_u32(sA);
    const uint32_t sB_u = smem_u32(sB);
    const uint32_t dstA = sA_u + (rowT * TSTRIDE + eT) * 2;
    const uint32_t dstB = sB_u + (rowT * TSTRIDE + eT) * 2;

    // ldmatrix base addresses (stage 0, ks = 0)
    uint32_t aAddr[2], bAddr[4];
    #pragma unroll
    for (int mt = 0; mt < 2; mt++)
        aAddr[mt] = sA_u + (((wm * 32 + mt * 16 + (lane & 15)) * TSTRIDE) +
                            ((lane >> 4) * 8)) * 2;
    #pragma unroll
    for (int ntp = 0; ntp < 4; ntp++)
        bAddr[ntp] = sB_u + (((wn * 64 + ntp * 16 + ((lane >> 4) * 8) + (lane & 7)) * TSTRIDE) +
                             (((lane >> 3) & 1) * 8)) * 2;

    // prologue: stage 0
    CP16(dstA,      srcA);
    CP16(dstA + 16, srcA + 8);
    CP16(dstB,      srcB);
    CP16(dstB + 16, srcB + 8);
    CP_COMMIT();

    for (int c = 0; c < 25; c++) {
        // stage c ready (its group was committed at iteration c-1 / prologue)
        CP_WAIT(0);
        // one barrier: publishes stage c to all warps AND proves all warps
        // finished compute of c-1 -> safe to overwrite stage (c+1)&1 below
        __syncthreads();
        if (c < 24) {
            const uint32_t pOff = (uint32_t)((c + 1) & 1) * STAGEB;
            const int k0 = (c + 1) * 32;
            CP16(dstA + pOff,      srcA + k0);
            CP16(dstA + pOff + 16, srcA + k0 + 8);
            CP16(dstB + pOff,      srcB + k0);
            CP16(dstB + pOff + 16, srcB + k0 + 8);
            CP_COMMIT();
        }
        const uint32_t stOff = (uint32_t)(c & 1) * STAGEB;
        #pragma unroll
        for (int ks = 0; ks < 2; ks++) {
            const uint32_t ko = stOff + ks * 32;   // 16 bf16 = 32 B
            uint32_t a[2][4], bf[8][2];
            LDSM_X4(a[0][0], a[0][1], a[0][2], a[0][3], aAddr[0] + ko);
            LDSM_X4(a[1][0], a[1][1], a[1][2], a[1][3], aAddr[1] + ko);
            LDSM_X4(bf[0][0], bf[0][1], bf[1][0], bf[1][1], bAddr[0] + ko);
            LDSM_X4(bf[2][0], bf[2][1], bf[3][0], bf[3][1], bAddr[1] + ko);
            LDSM_X4(bf[4][0], bf[4][1], bf[5][0], bf[5][1], bAddr[2] + ko);
            LDSM_X4(bf[6][0], bf[6][1], bf[7][0], bf[7][1], bAddr[3] + ko);
            #pragma unroll
            for (int mt = 0; mt < 2; mt++)
                #pragma unroll
                for (int nt = 0; nt < 8; nt++)
                    asm volatile(
                        "mma.sync.aligned.m16n8k16.row.col.f32.bf16.bf16.f32 "
                        "{%0,%1,%2,%3},{%4,%5,%6,%7},{%8,%9},{%0,%1,%2,%3};"
                        : "+f"(acc[mt][nt][0]), "+f"(acc[mt][nt][1]),
                          "+f"(acc[mt][nt][2]), "+f"(acc[mt][nt][3])
                        : "r"(a[mt][0]), "r"(a[mt][1]), "r"(a[mt][2]), "r"(a[mt][3]),
                          "r"(bf[nt][0]), "r"(bf[nt][1]));
        }
    }

    // ---- stage 2 straight from fragments ----
    float lg[4][OUT_];
    #pragma unroll
    for (int r = 0; r < 4; r++)
        #pragma unroll
        for (int o = 0; o < OUT_; o++) lg[r][o] = 0.f;

    #pragma unroll
    for (int nt = 0; nt < 8; nt++) {
        #pragma unroll
        for (int e = 0; e < 2; e++) {
            const int j = nt * 8 + 2 * t + e;
            const float bias = b1s[wn * 64 + j];
            float wv[OUT_];
            #pragma unroll
            for (int o = 0; o < OUT_; o++) wv[o] = w2s[wn * 640 + o * 64 + j];
            #pragma unroll
            for (int mt = 0; mt < 2; mt++)
                #pragma unroll
                for (int h = 0; h < 2; h++) {
                    float hv = fmaxf(acc[mt][nt][h * 2 + e] + bias, 0.f);
                    #pragma unroll
                    for (int o = 0; o < OUT_; o++)
                        lg[mt * 2 + h][o] = fmaf(hv, wv[o], lg[mt * 2 + h][o]);
                }
        }
    }
    #pragma unroll
    for (int r = 0; r < 4; r++)
        #pragma unroll
        for (int o = 0; o < OUT_; o++) {
            lg[r][o] += __shfl_xor_sync(0xffffffffu, lg[r][o], 1);
            lg[r][o] += __shfl_xor_sync(0xffffffffu, lg[r][o], 2);
        }

    float ce = 0.f;
    if (t == 0) {
        const int bidx = 2 * bp + wn;
        #pragma unroll
        for (int mt = 0; mt < 2; mt++)
            #pragma unroll
            for (int h = 0; h < 2; h++) {
                const int gn = n0 + wm * 32 + mt * 16 + g + 8 * h;
                if (gn < NTEST) {
                    float logits[OUT_];
                    #pragma unroll
                    for (int o = 0; o < OUT_; o++)
                        logits[o] = lg[mt * 2 + h][o] + b2s[wn * 10 + o];
                    float m = logits[0];
                    #pragma unroll
                    for (int o = 1; o < OUT_; o++) m = fmaxf(m, logits[o]);
                    float s = 0.f;
                    #pragma unroll
                    for (int o = 0; o < OUT_; o++) s += expf(logits[o] - m);
                    float lse = m + logf(s);
                    int tg = tar2[(size_t)bidx * NTEST + gn];
                    float picked = 0.f;
                    #pragma unroll
                    for (int o = 0; o < OUT_; o++) picked = (o == tg) ? logits[o] : picked;
                    ce += lse - picked;
                }
            }
    }
    #pragma unroll
    for (int off = 16; off; off >>= 1) ce += __shfl_down_sync(0xffffffffu, ce, off);
    if (lane == 0) warpsum[wid] = ce;
    __syncthreads();
    if (tid == 0) {
        float tot = 0.f;
        #pragma unroll
        for (int i = 0; i < 8; i++) tot += warpsum[i];
        atomicAdd(&g_acc2, (double)tot);
    }
}

// ---------------- finalize: reduce loss1 partials + combine ----------------
__global__ __launch_bounds__(256) void fin_k(float* __restrict__ out) {
    __shared__ float ws[8];
    float s = 0.f;
    for (int i = threadIdx.x; i < PREPB; i += 256) s += g_l1part[i];
    #pragma unroll
    for (int off = 16; off; off >>= 1) s += __shfl_down_sync(0xffffffffu, s, off);
    int lane = threadIdx.x & 31, wrp = threadIdx.x >> 5;
    if (lane == 0) ws[wrp] = s;
    __syncthreads();
    if (threadIdx.x == 0) {
        float tot = 0.f;
        #pragma unroll
        for (int i = 0; i < 8; i++) tot += ws[i];
        float l1 = (float)(20.0 * ((double)tot / (double)((size_t)B_ * WVEC)));
        float l2 = (float)(g_acc2 / (double)((size_t)B_ * NTEST));
        out[0] = l1 + l2;
        out[1] = l1;
        out[2] = l2;
    }
}

extern "C" void kernel_launch(void* const* d_in, const int* in_sizes, int n_in,
                              void* d_out, int out_size) {
    const float* inp1   = (const float*)d_in[0];
    const float* tar1   = (const float*)d_in[1];
    const float* inp2   = (const float*)d_in[2];
    const int*   tar2   = (const int*)d_in[3];
    const float* images = (const float*)d_in[4];
    float* out = (float*)d_out;

    prep_k<<<PREPB, 256>>>(images, inp2, inp1, tar1);
    dim3 grid(NTILE_, B_ / 2);
    mlp_ce_mma_k<<<grid, 256>>>(inp2, tar2);
    fin_k<<<1, 256>>>(out);
}